// round 15
// baseline (speedup 1.0000x reference)
#include <cuda_runtime.h>
#include <cuda_fp8.h>
#include <math.h>
#include <stdint.h>

#define NPTS 8192
#define DIM 32
#define MB 32
#define S 4
#define SPLITC 2048          // knn: cols per split
#define CHUNK 128            // knn: cols per staged chunk
#define NCHK (SPLITC / CHUNK)   // 16
#define NTPC (CHUNK / 8)        // 16
#define BROW 48
#define CSPLIT 1024          // count: cols per split
#define CCHUNK 64
#define CNCHK (CSPLIT / CCHUNK) // 16
#define CNTPC (CCHUNK / 8)      // 8

__device__ float g_rho_sq[2][NPTS];
__device__ int   g_kp[2][NPTS];
__device__ int   g_kpsum[2];
__device__ float g_r[2];
__device__ unsigned int g_done;
__device__ __align__(16) float g_nrm[2][NPTS];   // [0]=P, [1]=Q
__device__ __align__(16) unsigned char g_bA[2][NPTS][DIM];  // e4m3(-2x)
__device__ __align__(16) unsigned char g_bB[2][NPTS][DIM];  // e4m3(x)

__device__ __forceinline__ void qmma(float* c, const uint32_t* a, uint32_t b0, uint32_t b1) {
    asm volatile(
        "mma.sync.aligned.m16n8k32.row.col.f32.e4m3.e4m3.f32 "
        "{%0,%1,%2,%3}, {%4,%5,%6,%7}, {%8,%9}, {%0,%1,%2,%3};"
        : "+f"(c[0]), "+f"(c[1]), "+f"(c[2]), "+f"(c[3])
        : "r"(a[0]), "r"(a[1]), "r"(a[2]), "r"(a[3]), "r"(b0), "r"(b1));
}
__device__ __forceinline__ void ins4(float& m0, float& m1, float& m2, float& m3, float s) {
    if (s < m3) {
        m3 = s;
        float t;
        if (m3 < m2) { t = m2; m2 = m3; m3 = t; }
        if (m2 < m1) { t = m1; m1 = m2; m2 = t; }
        if (m1 < m0) { t = m0; m0 = m1; m1 = t; }
    }
}

// ---------------- prep ------------------------------------------------------
__global__ void prep_kernel(const float* __restrict__ P, const float* __restrict__ Q) {
    int t = blockIdx.x * blockDim.x + threadIdx.x;
    if (t == 0) {
        g_r[0] = 0.f; g_r[1] = 0.f;
        g_kpsum[0] = 0; g_kpsum[1] = 0;
        g_done = 0u;
    }
    if (t >= 2 * NPTS) return;
    int w = (t >= NPTS);
    int row = w ? t - NPTS : t;
    const float4* r4 = (const float4*)((w ? Q : P) + (size_t)row * DIM);
    float na = 0.f;
    unsigned char ra[DIM], rb[DIM];
#pragma unroll
    for (int i = 0; i < DIM / 4; i++) {
        float4 x = r4[i];
        na = fmaf(x.x, x.x, na); na = fmaf(x.y, x.y, na);
        na = fmaf(x.z, x.z, na); na = fmaf(x.w, x.w, na);
        const float v[4] = {x.x, x.y, x.z, x.w};
#pragma unroll
        for (int e = 0; e < 4; e++) {
            ra[4 * i + e] = __nv_cvt_float_to_fp8(-2.f * v[e], __NV_SATFINITE, __NV_E4M3);
            rb[4 * i + e] = __nv_cvt_float_to_fp8(v[e], __NV_SATFINITE, __NV_E4M3);
        }
    }
    g_nrm[w][row] = na;
    g_kp[w][row] = 0;
    uint4* da = (uint4*)g_bA[w][row];
    uint4* db = (uint4*)g_bB[w][row];
#pragma unroll
    for (int q = 0; q < 2; q++) { da[q] = ((uint4*)ra)[q]; db[q] = ((uint4*)rb)[q]; }
}

// ---------------- knn pass (R14 single-sync, both dirs) ----------------------
__global__ void __launch_bounds__(256) knn_pass() {
    __shared__ __align__(16) unsigned char smD[2][S][CHUNK * BROW];  // 48 KB
    __shared__ __align__(16) float smN[2][S][CHUNK];                 //  4 KB

    const int tid = threadIdx.x;
    const int w = tid >> 5, lane = tid & 31;
    const int g = lane >> 2, lam = lane & 3;
    const int rg = w & 1, sp = w >> 1;
    const int sel = blockIdx.y;
    const int setA = sel ? 0 : 1;
    const int r0 = blockIdx.x * MB + rg * 16 + g;

    uint32_t A[4];
    {
        const unsigned char* ab = (const unsigned char*)g_bA[setA] + (size_t)r0 * 32 + 4 * lam;
        A[0] = *(const uint32_t*)(ab);
        A[1] = *(const uint32_t*)(ab + 8 * 32);
        A[2] = *(const uint32_t*)(ab + 16);
        A[3] = *(const uint32_t*)(ab + 8 * 32 + 16);
    }
    float m0 = 3.4e38f, m1 = 3.4e38f, m2 = 3.4e38f, m3 = 3.4e38f;
    float n0 = 3.4e38f, n1 = 3.4e38f, n2 = 3.4e38f, n3 = 3.4e38f;

    const int sp2 = tid >> 6, rr = tid & 63;
    const unsigned char* bB = (const unsigned char*)g_bB[setA] + (size_t)(sp2 * SPLITC + rr) * 32;
    const unsigned char* nB = (const unsigned char*)(g_nrm[setA] + sp2 * SPLITC) + rr * 16;

    {
        uint4 v0 = *(const uint4*)(bB);
        uint4 v1 = *(const uint4*)(bB + 16);
        uint4 v2 = *(const uint4*)(bB + 64 * 32);
        uint4 v3 = *(const uint4*)(bB + 64 * 32 + 16);
        *(uint4*)(&smD[0][sp2][rr * BROW])             = v0;
        *(uint4*)(&smD[0][sp2][rr * BROW + 16])        = v1;
        *(uint4*)(&smD[0][sp2][(rr + 64) * BROW])      = v2;
        *(uint4*)(&smD[0][sp2][(rr + 64) * BROW + 16]) = v3;
        if (rr < 32) *(uint4*)((unsigned char*)smN[0][sp2] + rr * 16) = *(const uint4*)nB;
    }

    for (int ci = 0; ci < NCHK; ci++) {
        uint4 p0, p1, p2, p3, pn;
        if (ci < NCHK - 1) {
            const unsigned char* src = bB + (size_t)(ci + 1) * CHUNK * 32;
            p0 = *(const uint4*)(src);
            p1 = *(const uint4*)(src + 16);
            p2 = *(const uint4*)(src + 64 * 32);
            p3 = *(const uint4*)(src + 64 * 32 + 16);
            if (rr < 32) pn = *(const uint4*)(nB + (size_t)(ci + 1) * CHUNK * 4);
        }
        __syncthreads();
        const unsigned char* buf = smD[ci & 1][sp];
        const float* nrm = smN[ci & 1][sp];
#pragma unroll
        for (int nt = 0; nt < NTPC; nt++) {
            float c[4] = {0.f, 0.f, 0.f, 0.f};
            const unsigned char* bb = buf + (nt * 8 + g) * BROW + 4 * lam;
            qmma(c, A, *(const uint32_t*)(bb), *(const uint32_t*)(bb + 16));
            float2 nb = *(const float2*)(nrm + nt * 8 + 2 * lam);
            float s0 = c[0] + nb.x, s1 = c[1] + nb.y;
            if (fminf(s0, s1) < m3) { ins4(m0, m1, m2, m3, s0); ins4(m0, m1, m2, m3, s1); }
            float s2 = c[2] + nb.x, s3 = c[3] + nb.y;
            if (fminf(s2, s3) < n3) { ins4(n0, n1, n2, n3, s2); ins4(n0, n1, n2, n3, s3); }
        }
        if (ci < NCHK - 1) {
            int b = (ci + 1) & 1;
            *(uint4*)(&smD[b][sp2][rr * BROW])             = p0;
            *(uint4*)(&smD[b][sp2][rr * BROW + 16])        = p1;
            *(uint4*)(&smD[b][sp2][(rr + 64) * BROW])      = p2;
            *(uint4*)(&smD[b][sp2][(rr + 64) * BROW + 16]) = p3;
            if (rr < 32) *(uint4*)((unsigned char*)smN[b][sp2] + rr * 16) = pn;
        }
    }

#pragma unroll
    for (int d = 1; d <= 2; d <<= 1) {
        float t0 = __shfl_xor_sync(0xffffffffu, m0, d);
        float t1 = __shfl_xor_sync(0xffffffffu, m1, d);
        float t2 = __shfl_xor_sync(0xffffffffu, m2, d);
        float t3 = __shfl_xor_sync(0xffffffffu, m3, d);
        ins4(m0, m1, m2, m3, t0); ins4(m0, m1, m2, m3, t1);
        ins4(m0, m1, m2, m3, t2); ins4(m0, m1, m2, m3, t3);
        float u0 = __shfl_xor_sync(0xffffffffu, n0, d);
        float u1 = __shfl_xor_sync(0xffffffffu, n1, d);
        float u2 = __shfl_xor_sync(0xffffffffu, n2, d);
        float u3 = __shfl_xor_sync(0xffffffffu, n3, d);
        ins4(n0, n1, n2, n3, u0); ins4(n0, n1, n2, n3, u1);
        ins4(n0, n1, n2, n3, u2); ins4(n0, n1, n2, n3, u3);
    }
    __syncthreads();
    float* smM = (float*)smD;
    if (lam == 0) {
        float* d0 = &smM[(sp * MB + rg * 16 + g) * 4];
        d0[0] = m0; d0[1] = m1; d0[2] = m2; d0[3] = m3;
        float* d1 = &smM[(sp * MB + rg * 16 + g + 8) * 4];
        d1[0] = n0; d1[1] = n1; d1[2] = n2; d1[3] = n3;
    }
    __syncthreads();
    if (tid < MB) {
        float q0 = 3.4e38f, q1 = 3.4e38f, q2 = 3.4e38f, q3 = 3.4e38f;
#pragma unroll
        for (int spq = 0; spq < S; spq++) {
            const float* src = &smM[(spq * MB + tid) * 4];
            ins4(q0, q1, q2, q3, src[0]); ins4(q0, q1, q2, q3, src[1]);
            ins4(q0, q1, q2, q3, src[2]); ins4(q0, q1, q2, q3, src[3]);
        }
        int row = blockIdx.x * MB + tid;
        g_rho_sq[sel][row] = fmaxf(q3 + g_nrm[setA][row], 1e-12f);
    }
}

// ---------------- merged count pass (R12, uncapped regs) ----------------------
// One sweep of D(Q,P). Rows = Q (vs rho[0]) -> kp[0]; cols = P (vs rho[1]) -> kp[1].
__global__ void __launch_bounds__(256) count_pass() {
    __shared__ __align__(16) unsigned char smD[2][S][CCHUNK * BROW];  // 24 KB
    __shared__ __align__(16) float smN[2][S][CCHUNK];
    __shared__ __align__(16) float smU[2][S][CCHUNK];
    __shared__ uint16_t smC[8][CSPLIT];                               // 16 KB
    __shared__ int smR[8];

    const int tid = threadIdx.x;
    const int w = tid >> 5, lane = tid & 31;
    const int g = lane >> 2, lam = lane & 3;
    const int rg = w & 1, sp = w >> 1;
    const int r0 = blockIdx.x * MB + rg * 16 + g;
    const int cb0 = blockIdx.y * (S * CSPLIT);

    for (int i = tid; i < 8 * CSPLIT / 2; i += 256) ((uint32_t*)smC)[i] = 0;

    uint32_t A[4];
    {
        const unsigned char* ab = (const unsigned char*)g_bA[1] + (size_t)r0 * 32 + 4 * lam;  // Q rows
        A[0] = *(const uint32_t*)(ab);
        A[1] = *(const uint32_t*)(ab + 8 * 32);
        A[2] = *(const uint32_t*)(ab + 16);
        A[3] = *(const uint32_t*)(ab + 8 * 32 + 16);
    }
    const float na0 = g_nrm[1][r0], na1 = g_nrm[1][r0 + 8];
    const float th0 = g_rho_sq[0][r0] - na0;
    const float th1 = g_rho_sq[0][r0 + 8] - na1;
    int cnt0 = 0, cnt1 = 0;

    const int sp2 = tid >> 6, rr = tid & 63;
    const int cbase = cb0 + sp2 * CSPLIT;
    const unsigned char* bB = (const unsigned char*)g_bB[0] + (size_t)(cbase + rr) * 32;  // P cols
    const unsigned char* nB = (const unsigned char*)(g_nrm[0] + cbase) + rr * 16;
    const unsigned char* rB = (const unsigned char*)(g_rho_sq[1] + cbase) + rr * 16;

    {
        uint4 v0 = *(const uint4*)(bB);
        uint4 v1 = *(const uint4*)(bB + 16);
        *(uint4*)(&smD[0][sp2][rr * BROW])      = v0;
        *(uint4*)(&smD[0][sp2][rr * BROW + 16]) = v1;
        if (rr < 16) {
            float4 nv = *(const float4*)nB;
            float4 rv = *(const float4*)rB;
            *(float4*)((unsigned char*)smN[0][sp2] + rr * 16) = nv;
            *(float4*)((unsigned char*)smU[0][sp2] + rr * 16) =
                make_float4(rv.x - nv.x, rv.y - nv.y, rv.z - nv.z, rv.w - nv.w);
        }
    }
    __syncthreads();

    for (int ci = 0; ci < CNCHK; ci++) {
        uint4 p0, p1;
        float4 pn, pr;
        if (ci < CNCHK - 1) {
            const unsigned char* src = bB + (size_t)(ci + 1) * CCHUNK * 32;
            p0 = *(const uint4*)(src);
            p1 = *(const uint4*)(src + 16);
            if (rr < 16) {
                pn = *(const float4*)(nB + (size_t)(ci + 1) * CCHUNK * 4);
                pr = *(const float4*)(rB + (size_t)(ci + 1) * CCHUNK * 4);
            }
        }
        const unsigned char* buf = smD[ci & 1][sp];
        const float* nrm = smN[ci & 1][sp];
        const float* ucol = smU[ci & 1][sp];
#pragma unroll
        for (int nt = 0; nt < CNTPC; nt++) {
            float c[4] = {0.f, 0.f, 0.f, 0.f};
            const unsigned char* bb = buf + (nt * 8 + g) * BROW + 4 * lam;
            qmma(c, A, *(const uint32_t*)(bb), *(const uint32_t*)(bb + 16));
            float2 nb = *(const float2*)(nrm + nt * 8 + 2 * lam);
            float2 u2 = *(const float2*)(ucol + nt * 8 + 2 * lam);
            cnt0 += (c[0] <= th0 - nb.x) ? 1 : 0;
            cnt0 += (c[1] <= th0 - nb.y) ? 1 : 0;
            cnt1 += (c[2] <= th1 - nb.x) ? 1 : 0;
            cnt1 += (c[3] <= th1 - nb.y) ? 1 : 0;
            uint32_t b0 = __ballot_sync(0xffffffffu, c[0] + na0 <= u2.x);
            uint32_t b1 = __ballot_sync(0xffffffffu, c[1] + na0 <= u2.y);
            uint32_t b2 = __ballot_sync(0xffffffffu, c[2] + na1 <= u2.x);
            uint32_t b3 = __ballot_sync(0xffffffffu, c[3] + na1 <= u2.y);
            if (lane < 8) {
                uint32_t mask = 0x11111111u << (lane >> 1);
                uint32_t pa = (lane & 1) ? b1 : b0;
                uint32_t pb = (lane & 1) ? b3 : b2;
                smC[w][ci * CCHUNK + nt * 8 + lane] =
                    (uint16_t)(__popc(pa & mask) + __popc(pb & mask));
            }
        }
        __syncthreads();
        if (ci < CNCHK - 1) {
            int b = (ci + 1) & 1;
            *(uint4*)(&smD[b][sp2][rr * BROW])      = p0;
            *(uint4*)(&smD[b][sp2][rr * BROW + 16]) = p1;
            if (rr < 16) {
                *(float4*)((unsigned char*)smN[b][sp2] + rr * 16) = pn;
                *(float4*)((unsigned char*)smU[b][sp2] + rr * 16) =
                    make_float4(pr.x - pn.x, pr.y - pn.y, pr.z - pn.z, pr.w - pn.w);
            }
        }
        __syncthreads();
    }

    int rowtot = cnt0 + cnt1;
#pragma unroll
    for (int d = 16; d; d >>= 1) rowtot += __shfl_xor_sync(0xffffffffu, rowtot, d);
    if (lane == 0) smR[w] = rowtot;

    cnt0 += __shfl_xor_sync(0xffffffffu, cnt0, 1);
    cnt0 += __shfl_xor_sync(0xffffffffu, cnt0, 2);
    cnt1 += __shfl_xor_sync(0xffffffffu, cnt1, 1);
    cnt1 += __shfl_xor_sync(0xffffffffu, cnt1, 2);
    if (lam == 0) {
        atomicAdd(&g_kp[0][r0], cnt0);
        atomicAdd(&g_kp[0][r0 + 8], cnt1);
    }
    __syncthreads();
    if (tid == 0) {
        int t = 0;
#pragma unroll
        for (int q = 0; q < 8; q++) t += smR[q];
        atomicAdd(&g_kpsum[0], t);
    }

    int coltot = 0;
    for (int i = tid; i < S * CSPLIT; i += 256) {
        int spq = i >> 10, c = i & (CSPLIT - 1);
        int tot = (int)smC[2 * spq][c] + (int)smC[2 * spq + 1][c];
        coltot += tot;
        atomicAdd(&g_kp[1][cb0 + spq * CSPLIT + c], tot);
    }
#pragma unroll
    for (int d = 16; d; d >>= 1) coltot += __shfl_xor_sync(0xffffffffu, coltot, d);
    if (lane == 0) smR[w] = coltot;
    __syncthreads();
    if (tid == 0) {
        int t = 0;
#pragma unroll
        for (int q = 0; q < 8; q++) t += smR[q];
        atomicAdd(&g_kpsum[1], t);
    }
}

// ---------------- fused final (32 blocks; last block writes out) --------------
__global__ void final_kernel(float* __restrict__ out) {
    __shared__ float sf[2][8];
    const int b = blockIdx.x, tid = threadIdx.x, lane = tid & 31, wp = tid >> 5;
    const float kpsum0 = (float)g_kpsum[0] + 1e-20f;
    const float kpsum1 = (float)g_kpsum[1] + 1e-20f;

    const float cq = 3.0f / 24576.0f;
    float r0 = 0.f, r1 = 0.f;
    {
        int j = b * 256 + tid;
        {
            float nu = sqrtf(g_rho_sq[0][j]);
            float p2 = nu * nu, p4 = p2 * p2, p8 = p4 * p4, p16 = p8 * p8, p32 = p16 * p16;
            float inv = 1.0f / (p32 + 1e-20f);
            float p_den = fminf(fmaxf((float)g_kp[0][j] / kpsum0 * inv, 1e-20f), 1e10f);
            float q_den = fminf(fmaxf(cq * inv, 1e-20f), 1e10f);
            r0 += (p_den / q_den) * cq;
        }
        {
            float nu = sqrtf(g_rho_sq[1][j]);
            float p2 = nu * nu, p4 = p2 * p2, p8 = p4 * p4, p16 = p8 * p8, p32 = p16 * p16;
            float inv = 1.0f / (p32 + 1e-20f);
            float p_den = fminf(fmaxf((float)g_kp[1][j] / kpsum1 * inv, 1e-20f), 1e10f);
            float q_den = fminf(fmaxf(cq * inv, 1e-20f), 1e10f);
            r1 += (p_den / q_den) * cq;
        }
    }
#pragma unroll
    for (int d = 16; d; d >>= 1) {
        r0 += __shfl_xor_sync(0xffffffffu, r0, d);
        r1 += __shfl_xor_sync(0xffffffffu, r1, d);
    }
    if (lane == 0) { sf[0][wp] = r0; sf[1][wp] = r1; }
    __syncthreads();
    if (tid == 0) {
        float a0 = 0.f, a1 = 0.f;
#pragma unroll
        for (int q = 0; q < 8; q++) { a0 += sf[0][q]; a1 += sf[1][q]; }
        atomicAdd(&g_r[0], a0);
        atomicAdd(&g_r[1], a1);
        __threadfence();
        unsigned int ticket = atomicAdd(&g_done, 1u);
        if (ticket == 31u) {
            float v0 = fmaxf(0.0f, logf(g_r[0]));
            float v1 = fmaxf(0.0f, logf(g_r[1]));
            out[0] = fmaxf(v0, v1);
        }
    }
}

// ---------------- launch -----------------------------------------------------
extern "C" void kernel_launch(void* const* d_in, const int* in_sizes, int n_in,
                              void* d_out, int out_size) {
    const float* P = (const float*)d_in[0];
    const float* Q = (const float*)d_in[1];
    float* out = (float*)d_out;

    prep_kernel<<<(2 * NPTS + 255) / 256, 256>>>(P, Q);
    knn_pass<<<dim3(NPTS / MB, 2), 256>>>();        // 4th-NN radii, both sets
    count_pass<<<dim3(NPTS / MB, 2), 256>>>();      // merged counts, one D(Q,P) sweep
    final_kernel<<<32, 256>>>(out);
}

// round 16
// speedup vs baseline: 1.0495x; 1.0495x over previous
#include <cuda_runtime.h>
#include <cuda_fp8.h>
#include <math.h>
#include <stdint.h>

#define NPTS 8192
#define DIM 32
#define MB 32
#define S 4
#define SPLITC 2048          // knn: cols per split
#define CHUNK 128            // knn: cols per staged chunk
#define NCHK (SPLITC / CHUNK)   // 16
#define NTPC (CHUNK / 8)        // 16
#define BROW 48
#define CSPLIT 1024          // count: cols per split
#define CCHUNK 64
#define CNCHK (CSPLIT / CCHUNK) // 16
#define CNTPC (CCHUNK / 8)      // 8

__device__ float g_rho_sq[2][NPTS];
__device__ int   g_kp[2][NPTS];
__device__ int   g_kpsum[2];
__device__ float g_r[2];
__device__ unsigned int g_done;
__device__ __align__(16) float g_nrm[2][NPTS];   // [0]=P, [1]=Q
__device__ __align__(16) unsigned char g_bA[2][NPTS][DIM];  // e4m3(-2x)
__device__ __align__(16) unsigned char g_bB[2][NPTS][DIM];  // e4m3(x)

__device__ __forceinline__ void qmma(float* c, const uint32_t* a, uint32_t b0, uint32_t b1) {
    asm volatile(
        "mma.sync.aligned.m16n8k32.row.col.f32.e4m3.e4m3.f32 "
        "{%0,%1,%2,%3}, {%4,%5,%6,%7}, {%8,%9}, {%0,%1,%2,%3};"
        : "+f"(c[0]), "+f"(c[1]), "+f"(c[2]), "+f"(c[3])
        : "r"(a[0]), "r"(a[1]), "r"(a[2]), "r"(a[3]), "r"(b0), "r"(b1));
}
__device__ __forceinline__ void ins4(float& m0, float& m1, float& m2, float& m3, float s) {
    if (s < m3) {
        m3 = s;
        float t;
        if (m3 < m2) { t = m2; m2 = m3; m3 = t; }
        if (m2 < m1) { t = m1; m1 = m2; m2 = t; }
        if (m1 < m0) { t = m0; m0 = m1; m1 = t; }
    }
}

// ---------------- prep ------------------------------------------------------
__global__ void prep_kernel(const float* __restrict__ P, const float* __restrict__ Q) {
    int t = blockIdx.x * blockDim.x + threadIdx.x;
    if (t == 0) {
        g_r[0] = 0.f; g_r[1] = 0.f;
        g_kpsum[0] = 0; g_kpsum[1] = 0;
        g_done = 0u;
    }
    if (t >= 2 * NPTS) return;
    int w = (t >= NPTS);
    int row = w ? t - NPTS : t;
    const float4* r4 = (const float4*)((w ? Q : P) + (size_t)row * DIM);
    float na = 0.f;
    unsigned char ra[DIM], rb[DIM];
#pragma unroll
    for (int i = 0; i < DIM / 4; i++) {
        float4 x = r4[i];
        na = fmaf(x.x, x.x, na); na = fmaf(x.y, x.y, na);
        na = fmaf(x.z, x.z, na); na = fmaf(x.w, x.w, na);
        const float v[4] = {x.x, x.y, x.z, x.w};
#pragma unroll
        for (int e = 0; e < 4; e++) {
            ra[4 * i + e] = __nv_cvt_float_to_fp8(-2.f * v[e], __NV_SATFINITE, __NV_E4M3);
            rb[4 * i + e] = __nv_cvt_float_to_fp8(v[e], __NV_SATFINITE, __NV_E4M3);
        }
    }
    g_nrm[w][row] = na;
    g_kp[w][row] = 0;
    uint4* da = (uint4*)g_bA[w][row];
    uint4* db = (uint4*)g_bB[w][row];
#pragma unroll
    for (int q = 0; q < 2; q++) { da[q] = ((uint4*)ra)[q]; db[q] = ((uint4*)rb)[q]; }
}

// ---------------- knn pass (single-sync, both dirs, uncapped) -----------------
__global__ void __launch_bounds__(256) knn_pass() {
    __shared__ __align__(16) unsigned char smD[2][S][CHUNK * BROW];  // 48 KB
    __shared__ __align__(16) float smN[2][S][CHUNK];                 //  4 KB

    const int tid = threadIdx.x;
    const int w = tid >> 5, lane = tid & 31;
    const int g = lane >> 2, lam = lane & 3;
    const int rg = w & 1, sp = w >> 1;
    const int sel = blockIdx.y;
    const int setA = sel ? 0 : 1;
    const int r0 = blockIdx.x * MB + rg * 16 + g;

    uint32_t A[4];
    {
        const unsigned char* ab = (const unsigned char*)g_bA[setA] + (size_t)r0 * 32 + 4 * lam;
        A[0] = *(const uint32_t*)(ab);
        A[1] = *(const uint32_t*)(ab + 8 * 32);
        A[2] = *(const uint32_t*)(ab + 16);
        A[3] = *(const uint32_t*)(ab + 8 * 32 + 16);
    }
    float m0 = 3.4e38f, m1 = 3.4e38f, m2 = 3.4e38f, m3 = 3.4e38f;
    float n0 = 3.4e38f, n1 = 3.4e38f, n2 = 3.4e38f, n3 = 3.4e38f;

    const int sp2 = tid >> 6, rr = tid & 63;
    const unsigned char* bB = (const unsigned char*)g_bB[setA] + (size_t)(sp2 * SPLITC + rr) * 32;
    const unsigned char* nB = (const unsigned char*)(g_nrm[setA] + sp2 * SPLITC) + rr * 16;

    {
        uint4 v0 = *(const uint4*)(bB);
        uint4 v1 = *(const uint4*)(bB + 16);
        uint4 v2 = *(const uint4*)(bB + 64 * 32);
        uint4 v3 = *(const uint4*)(bB + 64 * 32 + 16);
        *(uint4*)(&smD[0][sp2][rr * BROW])             = v0;
        *(uint4*)(&smD[0][sp2][rr * BROW + 16])        = v1;
        *(uint4*)(&smD[0][sp2][(rr + 64) * BROW])      = v2;
        *(uint4*)(&smD[0][sp2][(rr + 64) * BROW + 16]) = v3;
        if (rr < 32) *(uint4*)((unsigned char*)smN[0][sp2] + rr * 16) = *(const uint4*)nB;
    }

    for (int ci = 0; ci < NCHK; ci++) {
        uint4 p0, p1, p2, p3, pn;
        if (ci < NCHK - 1) {
            const unsigned char* src = bB + (size_t)(ci + 1) * CHUNK * 32;
            p0 = *(const uint4*)(src);
            p1 = *(const uint4*)(src + 16);
            p2 = *(const uint4*)(src + 64 * 32);
            p3 = *(const uint4*)(src + 64 * 32 + 16);
            if (rr < 32) pn = *(const uint4*)(nB + (size_t)(ci + 1) * CHUNK * 4);
        }
        __syncthreads();
        const unsigned char* buf = smD[ci & 1][sp];
        const float* nrm = smN[ci & 1][sp];
#pragma unroll
        for (int nt = 0; nt < NTPC; nt++) {
            float c[4] = {0.f, 0.f, 0.f, 0.f};
            const unsigned char* bb = buf + (nt * 8 + g) * BROW + 4 * lam;
            qmma(c, A, *(const uint32_t*)(bb), *(const uint32_t*)(bb + 16));
            float2 nb = *(const float2*)(nrm + nt * 8 + 2 * lam);
            float s0 = c[0] + nb.x, s1 = c[1] + nb.y;
            if (fminf(s0, s1) < m3) { ins4(m0, m1, m2, m3, s0); ins4(m0, m1, m2, m3, s1); }
            float s2 = c[2] + nb.x, s3 = c[3] + nb.y;
            if (fminf(s2, s3) < n3) { ins4(n0, n1, n2, n3, s2); ins4(n0, n1, n2, n3, s3); }
        }
        if (ci < NCHK - 1) {
            int b = (ci + 1) & 1;
            *(uint4*)(&smD[b][sp2][rr * BROW])             = p0;
            *(uint4*)(&smD[b][sp2][rr * BROW + 16])        = p1;
            *(uint4*)(&smD[b][sp2][(rr + 64) * BROW])      = p2;
            *(uint4*)(&smD[b][sp2][(rr + 64) * BROW + 16]) = p3;
            if (rr < 32) *(uint4*)((unsigned char*)smN[b][sp2] + rr * 16) = pn;
        }
    }

#pragma unroll
    for (int d = 1; d <= 2; d <<= 1) {
        float t0 = __shfl_xor_sync(0xffffffffu, m0, d);
        float t1 = __shfl_xor_sync(0xffffffffu, m1, d);
        float t2 = __shfl_xor_sync(0xffffffffu, m2, d);
        float t3 = __shfl_xor_sync(0xffffffffu, m3, d);
        ins4(m0, m1, m2, m3, t0); ins4(m0, m1, m2, m3, t1);
        ins4(m0, m1, m2, m3, t2); ins4(m0, m1, m2, m3, t3);
        float u0 = __shfl_xor_sync(0xffffffffu, n0, d);
        float u1 = __shfl_xor_sync(0xffffffffu, n1, d);
        float u2 = __shfl_xor_sync(0xffffffffu, n2, d);
        float u3 = __shfl_xor_sync(0xffffffffu, n3, d);
        ins4(n0, n1, n2, n3, u0); ins4(n0, n1, n2, n3, u1);
        ins4(n0, n1, n2, n3, u2); ins4(n0, n1, n2, n3, u3);
    }
    __syncthreads();
    float* smM = (float*)smD;
    if (lam == 0) {
        float* d0 = &smM[(sp * MB + rg * 16 + g) * 4];
        d0[0] = m0; d0[1] = m1; d0[2] = m2; d0[3] = m3;
        float* d1 = &smM[(sp * MB + rg * 16 + g + 8) * 4];
        d1[0] = n0; d1[1] = n1; d1[2] = n2; d1[3] = n3;
    }
    __syncthreads();
    if (tid < MB) {
        float q0 = 3.4e38f, q1 = 3.4e38f, q2 = 3.4e38f, q3 = 3.4e38f;
#pragma unroll
        for (int spq = 0; spq < S; spq++) {
            const float* src = &smM[(spq * MB + tid) * 4];
            ins4(q0, q1, q2, q3, src[0]); ins4(q0, q1, q2, q3, src[1]);
            ins4(q0, q1, q2, q3, src[2]); ins4(q0, q1, q2, q3, src[3]);
        }
        int row = blockIdx.x * MB + tid;
        g_rho_sq[sel][row] = fmaxf(q3 + g_nrm[setA][row], 1e-12f);
    }
}

// ---------------- merged count pass (R12 exact: capped (256,4)) ---------------
// One sweep of D(Q,P). Rows = Q (vs rho[0]) -> kp[0]; cols = P (vs rho[1]) -> kp[1].
__global__ void __launch_bounds__(256, 4) count_pass() {
    __shared__ __align__(16) unsigned char smD[2][S][CCHUNK * BROW];  // 24 KB
    __shared__ __align__(16) float smN[2][S][CCHUNK];
    __shared__ __align__(16) float smU[2][S][CCHUNK];
    __shared__ uint16_t smC[8][CSPLIT];                               // 16 KB
    __shared__ int smR[8];

    const int tid = threadIdx.x;
    const int w = tid >> 5, lane = tid & 31;
    const int g = lane >> 2, lam = lane & 3;
    const int rg = w & 1, sp = w >> 1;
    const int r0 = blockIdx.x * MB + rg * 16 + g;
    const int cb0 = blockIdx.y * (S * CSPLIT);

    for (int i = tid; i < 8 * CSPLIT / 2; i += 256) ((uint32_t*)smC)[i] = 0;

    uint32_t A[4];
    {
        const unsigned char* ab = (const unsigned char*)g_bA[1] + (size_t)r0 * 32 + 4 * lam;  // Q rows
        A[0] = *(const uint32_t*)(ab);
        A[1] = *(const uint32_t*)(ab + 8 * 32);
        A[2] = *(const uint32_t*)(ab + 16);
        A[3] = *(const uint32_t*)(ab + 8 * 32 + 16);
    }
    const float na0 = g_nrm[1][r0], na1 = g_nrm[1][r0 + 8];
    const float th0 = g_rho_sq[0][r0] - na0;
    const float th1 = g_rho_sq[0][r0 + 8] - na1;
    int cnt0 = 0, cnt1 = 0;

    const int sp2 = tid >> 6, rr = tid & 63;
    const int cbase = cb0 + sp2 * CSPLIT;
    const unsigned char* bB = (const unsigned char*)g_bB[0] + (size_t)(cbase + rr) * 32;  // P cols
    const unsigned char* nB = (const unsigned char*)(g_nrm[0] + cbase) + rr * 16;
    const unsigned char* rB = (const unsigned char*)(g_rho_sq[1] + cbase) + rr * 16;

    {
        uint4 v0 = *(const uint4*)(bB);
        uint4 v1 = *(const uint4*)(bB + 16);
        *(uint4*)(&smD[0][sp2][rr * BROW])      = v0;
        *(uint4*)(&smD[0][sp2][rr * BROW + 16]) = v1;
        if (rr < 16) {
            float4 nv = *(const float4*)nB;
            float4 rv = *(const float4*)rB;
            *(float4*)((unsigned char*)smN[0][sp2] + rr * 16) = nv;
            *(float4*)((unsigned char*)smU[0][sp2] + rr * 16) =
                make_float4(rv.x - nv.x, rv.y - nv.y, rv.z - nv.z, rv.w - nv.w);
        }
    }
    __syncthreads();

    for (int ci = 0; ci < CNCHK; ci++) {
        uint4 p0, p1;
        float4 pn, pr;
        if (ci < CNCHK - 1) {
            const unsigned char* src = bB + (size_t)(ci + 1) * CCHUNK * 32;
            p0 = *(const uint4*)(src);
            p1 = *(const uint4*)(src + 16);
            if (rr < 16) {
                pn = *(const float4*)(nB + (size_t)(ci + 1) * CCHUNK * 4);
                pr = *(const float4*)(rB + (size_t)(ci + 1) * CCHUNK * 4);
            }
        }
        const unsigned char* buf = smD[ci & 1][sp];
        const float* nrm = smN[ci & 1][sp];
        const float* ucol = smU[ci & 1][sp];
#pragma unroll
        for (int nt = 0; nt < CNTPC; nt++) {
            float c[4] = {0.f, 0.f, 0.f, 0.f};
            const unsigned char* bb = buf + (nt * 8 + g) * BROW + 4 * lam;
            qmma(c, A, *(const uint32_t*)(bb), *(const uint32_t*)(bb + 16));
            float2 nb = *(const float2*)(nrm + nt * 8 + 2 * lam);
            float2 u2 = *(const float2*)(ucol + nt * 8 + 2 * lam);
            cnt0 += (c[0] <= th0 - nb.x) ? 1 : 0;
            cnt0 += (c[1] <= th0 - nb.y) ? 1 : 0;
            cnt1 += (c[2] <= th1 - nb.x) ? 1 : 0;
            cnt1 += (c[3] <= th1 - nb.y) ? 1 : 0;
            uint32_t b0 = __ballot_sync(0xffffffffu, c[0] + na0 <= u2.x);
            uint32_t b1 = __ballot_sync(0xffffffffu, c[1] + na0 <= u2.y);
            uint32_t b2 = __ballot_sync(0xffffffffu, c[2] + na1 <= u2.x);
            uint32_t b3 = __ballot_sync(0xffffffffu, c[3] + na1 <= u2.y);
            if (lane < 8) {
                uint32_t mask = 0x11111111u << (lane >> 1);
                uint32_t pa = (lane & 1) ? b1 : b0;
                uint32_t pb = (lane & 1) ? b3 : b2;
                smC[w][ci * CCHUNK + nt * 8 + lane] =
                    (uint16_t)(__popc(pa & mask) + __popc(pb & mask));
            }
        }
        __syncthreads();
        if (ci < CNCHK - 1) {
            int b = (ci + 1) & 1;
            *(uint4*)(&smD[b][sp2][rr * BROW])      = p0;
            *(uint4*)(&smD[b][sp2][rr * BROW + 16]) = p1;
            if (rr < 16) {
                *(float4*)((unsigned char*)smN[b][sp2] + rr * 16) = pn;
                *(float4*)((unsigned char*)smU[b][sp2] + rr * 16) =
                    make_float4(pr.x - pn.x, pr.y - pn.y, pr.z - pn.z, pr.w - pn.w);
            }
        }
        __syncthreads();
    }

    int rowtot = cnt0 + cnt1;
#pragma unroll
    for (int d = 16; d; d >>= 1) rowtot += __shfl_xor_sync(0xffffffffu, rowtot, d);
    if (lane == 0) smR[w] = rowtot;

    cnt0 += __shfl_xor_sync(0xffffffffu, cnt0, 1);
    cnt0 += __shfl_xor_sync(0xffffffffu, cnt0, 2);
    cnt1 += __shfl_xor_sync(0xffffffffu, cnt1, 1);
    cnt1 += __shfl_xor_sync(0xffffffffu, cnt1, 2);
    if (lam == 0) {
        atomicAdd(&g_kp[0][r0], cnt0);
        atomicAdd(&g_kp[0][r0 + 8], cnt1);
    }
    __syncthreads();
    if (tid == 0) {
        int t = 0;
#pragma unroll
        for (int q = 0; q < 8; q++) t += smR[q];
        atomicAdd(&g_kpsum[0], t);
    }

    int coltot = 0;
    for (int i = tid; i < S * CSPLIT; i += 256) {
        int spq = i >> 10, c = i & (CSPLIT - 1);
        int tot = (int)smC[2 * spq][c] + (int)smC[2 * spq + 1][c];
        coltot += tot;
        atomicAdd(&g_kp[1][cb0 + spq * CSPLIT + c], tot);
    }
#pragma unroll
    for (int d = 16; d; d >>= 1) coltot += __shfl_xor_sync(0xffffffffu, coltot, d);
    if (lane == 0) smR[w] = coltot;
    __syncthreads();
    if (tid == 0) {
        int t = 0;
#pragma unroll
        for (int q = 0; q < 8; q++) t += smR[q];
        atomicAdd(&g_kpsum[1], t);
    }
}

// ---------------- fused final (32 blocks; last block writes out) --------------
__global__ void final_kernel(float* __restrict__ out) {
    __shared__ float sf[2][8];
    const int b = blockIdx.x, tid = threadIdx.x, lane = tid & 31, wp = tid >> 5;
    const float kpsum0 = (float)g_kpsum[0] + 1e-20f;
    const float kpsum1 = (float)g_kpsum[1] + 1e-20f;

    const float cq = 3.0f / 24576.0f;
    float r0 = 0.f, r1 = 0.f;
    {
        int j = b * 256 + tid;
        {
            float nu = sqrtf(g_rho_sq[0][j]);
            float p2 = nu * nu, p4 = p2 * p2, p8 = p4 * p4, p16 = p8 * p8, p32 = p16 * p16;
            float inv = 1.0f / (p32 + 1e-20f);
            float p_den = fminf(fmaxf((float)g_kp[0][j] / kpsum0 * inv, 1e-20f), 1e10f);
            float q_den = fminf(fmaxf(cq * inv, 1e-20f), 1e10f);
            r0 += (p_den / q_den) * cq;
        }
        {
            float nu = sqrtf(g_rho_sq[1][j]);
            float p2 = nu * nu, p4 = p2 * p2, p8 = p4 * p4, p16 = p8 * p8, p32 = p16 * p16;
            float inv = 1.0f / (p32 + 1e-20f);
            float p_den = fminf(fmaxf((float)g_kp[1][j] / kpsum1 * inv, 1e-20f), 1e10f);
            float q_den = fminf(fmaxf(cq * inv, 1e-20f), 1e10f);
            r1 += (p_den / q_den) * cq;
        }
    }
#pragma unroll
    for (int d = 16; d; d >>= 1) {
        r0 += __shfl_xor_sync(0xffffffffu, r0, d);
        r1 += __shfl_xor_sync(0xffffffffu, r1, d);
    }
    if (lane == 0) { sf[0][wp] = r0; sf[1][wp] = r1; }
    __syncthreads();
    if (tid == 0) {
        float a0 = 0.f, a1 = 0.f;
#pragma unroll
        for (int q = 0; q < 8; q++) { a0 += sf[0][q]; a1 += sf[1][q]; }
        atomicAdd(&g_r[0], a0);
        atomicAdd(&g_r[1], a1);
        __threadfence();
        unsigned int ticket = atomicAdd(&g_done, 1u);
        if (ticket == 31u) {
            float v0 = fmaxf(0.0f, logf(g_r[0]));
            float v1 = fmaxf(0.0f, logf(g_r[1]));
            out[0] = fmaxf(v0, v1);
        }
    }
}

// ---------------- launch -----------------------------------------------------
extern "C" void kernel_launch(void* const* d_in, const int* in_sizes, int n_in,
                              void* d_out, int out_size) {
    const float* P = (const float*)d_in[0];
    const float* Q = (const float*)d_in[1];
    float* out = (float*)d_out;

    prep_kernel<<<(2 * NPTS + 255) / 256, 256>>>(P, Q);
    knn_pass<<<dim3(NPTS / MB, 2), 256>>>();        // 4th-NN radii, both sets
    count_pass<<<dim3(NPTS / MB, 2), 256>>>();      // merged counts, one D(Q,P) sweep
    final_kernel<<<32, 256>>>(out);
}